// round 11
// baseline (speedup 1.0000x reference)
#include <cuda_runtime.h>
#include <cstdint>
#include <math.h>

typedef unsigned long long ull;

static constexpr int B_ROWS = 262144;
static constexpr int L_STEPS = 20;
static constexpr int TPB = 64;
static constexpr int ROWS_PER_CTA = 2 * TPB;                 // 128
static constexpr int GRID = B_ROWS / ROWS_PER_CTA;           // 2048

// ---- shared memory layout (floats) ----
// Persistent: sWdr[50*52]@0, sbdr[50]@2600, sbd[50]@2650, sb1[100]@2700,
//             sW2[100]@2800, sWfc[100]@2900, smisc[4]@3000
// Noise buffer @3008: [6400] floats; thread t owns words [t*100, t*100+100)
//   = rows (base+2t, base+2t+1), a contiguous 400B (16B-aligned) slice.
// Phase-1 aliases into the buffer sequentially: sWd[4800], then sW1[5200].
static constexpr int OFF_WDR   = 0;
static constexpr int OFF_BDR   = 2600;
static constexpr int OFF_BD    = 2650;
static constexpr int OFF_B1    = 2700;
static constexpr int OFF_W2    = 2800;
static constexpr int OFF_WFC   = 2900;
static constexpr int OFF_MISC  = 3000;
static constexpr int OFF_BUF   = 3008;                        // 16B aligned
static constexpr int NOISE_TILE = ROWS_PER_CTA * 50;          // 6400 floats (25.6 KB)
static constexpr int SMEM_FLOATS = OFF_BUF + NOISE_TILE;      // 9408
static constexpr int SMEM_BYTES  = SMEM_FLOATS * 4;           // 37632 -> 5 CTAs/SM

// ---- packed f32x2 helpers (Blackwell 2x-fp32 path; PTX-only) ----
static __device__ __forceinline__ ull ffma2(ull a, ull b, ull c) {
    ull d;
    asm("fma.rn.f32x2 %0, %1, %2, %3;" : "=l"(d) : "l"(a), "l"(b), "l"(c));
    return d;
}
static __device__ __forceinline__ ull pack2(float lo, float hi) {
    ull r;
    asm("mov.b64 %0, {%1, %2};" : "=l"(r) : "f"(lo), "f"(hi));
    return r;
}
static __device__ __forceinline__ void unpack2(ull v, float& lo, float& hi) {
    asm("mov.b64 {%0, %1}, %2;" : "=f"(lo), "=f"(hi) : "l"(v));
}

static __device__ __forceinline__ unsigned smem_u32(const void* p) {
    return (unsigned)__cvta_generic_to_shared(p);
}
static __device__ __forceinline__ void cp16(void* sdst, const void* gsrc) {
    asm volatile("cp.async.cg.shared.global [%0], [%1], 16;"
                 :: "r"(smem_u32(sdst)), "l"(gsrc) : "memory");
}

// Prologue dot for one row, chunked partial sums (bounded register pressure).
static __device__ __forceinline__ void prologue_row(const float* __restrict__ xrow,
                                                    const float* __restrict__ sWd,
                                                    const float* __restrict__ sbd,
                                                    ull* __restrict__ out2) {
#pragma unroll
    for (int p = 0; p < 25; ++p) out2[p] = pack2(sbd[2 * p], sbd[2 * p + 1]);

    for (int c = 0; c < 3; ++c) {
        ull xv[16];
        const ull* xr = (const ull*)xrow + c * 16;
        if (c < 2) {
#pragma unroll
            for (int t = 0; t < 16; ++t) xv[t] = xr[t];
        } else {
#pragma unroll
            for (int t = 0; t < 13; ++t) xv[t] = xr[t];
            xv[13] = 0ull; xv[14] = 0ull; xv[15] = 0ull;   // Wd cols 90..95 are 0
        }
#pragma unroll 5
        for (int p = 0; p < 25; ++p) {
            const ulonglong2* w0 = (const ulonglong2*)(sWd + (2 * p) * 96 + c * 32);
            const ulonglong2* w1 = (const ulonglong2*)(sWd + (2 * p + 1) * 96 + c * 32);
            ull a0 = 0ull, a1 = 0ull;
#pragma unroll
            for (int q = 0; q < 8; ++q) {
                ulonglong2 wa = w0[q];
                a0 = ffma2(wa.x, xv[2 * q],     a0);
                a0 = ffma2(wa.y, xv[2 * q + 1], a0);
                ulonglong2 wb = w1[q];
                a1 = ffma2(wb.x, xv[2 * q],     a1);
                a1 = ffma2(wb.y, xv[2 * q + 1], a1);
            }
            float l0, h0, l1, h1, o0, o1;
            unpack2(a0, l0, h0);
            unpack2(a1, l1, h1);
            unpack2(out2[p], o0, o1);
            out2[p] = pack2(o0 + l0 + h0, o1 + l1 + h1);
        }
    }
}

__global__ void __launch_bounds__(TPB, 5)   // 5 CTAs/SM -> 10 warps/SM, reg cap 204
sdenet_kernel(const float* __restrict__ x,      // [B,90]
              const float* __restrict__ Wd,     // [50,90]
              const float* __restrict__ bd,     // [50]
              const float* __restrict__ Wdrift, // [50,50]
              const float* __restrict__ bdrift, // [50]
              const float* __restrict__ W1,     // [100,50]
              const float* __restrict__ b1,     // [100]
              const float* __restrict__ W2,     // [1,100]
              const float* __restrict__ b2,     // [1]
              const float* __restrict__ Wfc,    // [2,50]
              const float* __restrict__ bfc,    // [2]
              const float* __restrict__ noise,  // [L,B,50]
              float* __restrict__ out)          // [2*B] = mean(B) ++ sigma(B)
{
    extern __shared__ float smem[];
    float* sWdr  = smem + OFF_WDR;
    float* sbdr  = smem + OFF_BDR;
    float* sbd   = smem + OFF_BD;
    float* sb1   = smem + OFF_B1;
    float* sW2   = smem + OFF_W2;
    float* sWfc  = smem + OFF_WFC;
    float* smisc = smem + OFF_MISC;
    float* sBuf  = smem + OFF_BUF;
    float* sWd   = sBuf;             // phase-1a alias (4800 <= 6400)
    float* sW1   = sBuf;             // phase-1b alias (5200 <= 6400)

    const int tid = threadIdx.x;
    const size_t rowBase = (size_t)blockIdx.x * ROWS_PER_CTA;
    const int rowA = (int)rowBase + 2 * tid;       // adjacent-row pair per thread
    const int rowB = rowA + 1;

    // Thread-private noise slice: 100 floats (rows 2t, 2t+1), 16B-aligned.
    float* mySlice = sBuf + tid * 100;
    // Global source offset of this thread's slice within a step tile.
    const size_t sliceOff = rowBase * 50 + (size_t)tid * 100;

    // ---- stage persistent weights + Wd (into buffer alias) ----
    for (int i = tid; i < 4800; i += TPB) {
        int r = i / 96, k = i - r * 96;
        sWd[i] = (k < 90) ? Wd[r * 90 + k] : 0.0f;
    }
    for (int i = tid; i < 2500; i += TPB) {
        int j = i / 50, k = i - j * 50;
        sWdr[j * 52 + k] = Wdrift[i];
    }
    for (int i = tid; i < 100; i += TPB) {
        sW2[i]  = W2[i];
        sb1[i]  = b1[i];
        sWfc[i] = Wfc[i];
    }
    if (tid < 50)  sbd[tid]  = bd[tid];
    if (tid < 50)  sbdr[tid] = bdrift[tid];
    if (tid == 0) { smisc[0] = b2[0]; smisc[1] = bfc[0]; smisc[2] = bfc[1]; }
    __syncthreads();

    // ================= prologue: out = x @ Wd^T + bd =================
    ull out2A[25], out2B[25];
    prologue_row(x + (size_t)rowA * 90, sWd, sbd, out2A);
    prologue_row(x + (size_t)rowB * 90, sWd, sbd, out2B);

    __syncthreads();   // done reading Wd; buffer free for W1

    // ---- stage W1 (into buffer alias) ----
    for (int i = tid; i < 5000; i += TPB) {
        int m = i / 50, k = i - m * 50;
        sW1[m * 52 + k] = W1[i];
    }
    __syncthreads();

    // ====== diffusion = 0.5*sigmoid(relu(out@W1^T+b1) @ W2^T + b2) ======
    float daccA = smisc[0], daccB = smisc[0];
#pragma unroll 2
    for (int m = 0; m < 100; ++m) {
        const float* wrow = sW1 + m * 52;
        const ulonglong2* w2r = (const ulonglong2*)wrow;
        ull aA = 0ull, aB = 0ull;
#pragma unroll
        for (int q = 0; q < 12; ++q) {
            ulonglong2 w = w2r[q];
            aA = ffma2(w.x, out2A[2 * q],     aA);
            aA = ffma2(w.y, out2A[2 * q + 1], aA);
            aB = ffma2(w.x, out2B[2 * q],     aB);
            aB = ffma2(w.y, out2B[2 * q + 1], aB);
        }
        ull wt = *(const ull*)(wrow + 48);
        aA = ffma2(wt, out2A[24], aA);
        aB = ffma2(wt, out2B[24], aB);
        float lA, hA, lB, hB;
        unpack2(aA, lA, hA);
        unpack2(aB, lB, hB);
        float bm = sb1[m], w2m = sW2[m];
        daccA = fmaf(w2m, fmaxf(lA + hA + bm, 0.0f), daccA);
        daccB = fmaf(w2m, fmaxf(lB + hB + bm, 0.0f), daccB);
    }
    const float dt   = 4.0f / 20.0f;
    const float sqdt = sqrtf(dt);
    const float diffA = 0.5f / (1.0f + expf(-daccA));
    const float diffB = 0.5f / (1.0f + expf(-daccB));
    const ull dsA = pack2(diffA * sqdt, diffA * sqdt);
    const ull dsB = pack2(diffB * sqdt, diffB * sqdt);
    const ull dt2 = pack2(dt, dt);

    __syncthreads();   // done reading W1; buffer free for noise (LAST CTA barrier)

    // ---- per-thread prefetch of step-0 noise slice (25 x cp16, own 400B) ----
    {
        const float* nsrc = noise + sliceOff;
        #pragma unroll
        for (int i = 0; i < 25; ++i)
            cp16(mySlice + i * 4, nsrc + i * 4);
        asm volatile("cp.async.commit_group;" ::: "memory");
    }

    // ================= main SDE loop: BARRIER-FREE =================
    // Each thread reads and refills only its own slice; cp.async groups are
    // per-thread, so no __syncthreads is needed anywhere in the loop.
#pragma unroll 1
    for (int l = 0; l < L_STEPS; ++l) {
        asm volatile("cp.async.wait_group 0;" ::: "memory");   // own slice ready

        const ull* nrowA = (const ull*)(mySlice);        // row 2t   (25 x f32x2)
        const ull* nrowB = (const ull*)(mySlice + 50);   // row 2t+1

        ull dnewA[25], dnewB[25];
#pragma unroll 5
        for (int p = 0; p < 25; ++p) {
            const float* w0 = sWdr + (2 * p) * 52;
            const float* w1 = w0 + 52;
            const ulonglong2* w02 = (const ulonglong2*)w0;
            const ulonglong2* w12 = (const ulonglong2*)w1;
            ull a0A = 0ull, a1A = 0ull, a0B = 0ull, a1B = 0ull;
#pragma unroll
            for (int q = 0; q < 12; ++q) {
                ulonglong2 wa = w02[q];
                a0A = ffma2(wa.x, out2A[2 * q],     a0A);
                a0A = ffma2(wa.y, out2A[2 * q + 1], a0A);
                a0B = ffma2(wa.x, out2B[2 * q],     a0B);
                a0B = ffma2(wa.y, out2B[2 * q + 1], a0B);
                ulonglong2 wb = w12[q];
                a1A = ffma2(wb.x, out2A[2 * q],     a1A);
                a1A = ffma2(wb.y, out2A[2 * q + 1], a1A);
                a1B = ffma2(wb.x, out2B[2 * q],     a1B);
                a1B = ffma2(wb.y, out2B[2 * q + 1], a1B);
            }
            ull wt0 = *(const ull*)(w0 + 48);
            ull wt1 = *(const ull*)(w1 + 48);
            a0A = ffma2(wt0, out2A[24], a0A);
            a1A = ffma2(wt1, out2A[24], a1A);
            a0B = ffma2(wt0, out2B[24], a0B);
            a1B = ffma2(wt1, out2B[24], a1B);

            float l0, h0, l1, h1;
            const float bd0 = sbdr[2 * p], bd1 = sbdr[2 * p + 1];

            unpack2(a0A, l0, h0);
            unpack2(a1A, l1, h1);
            {
                float s0 = fmaxf(l0 + h0 + bd0, 0.0f);
                float s1 = fmaxf(l1 + h1 + bd1, 0.0f);
                ull nv = ffma2(dt2, pack2(s0, s1), out2A[p]);
                dnewA[p] = ffma2(dsA, nrowA[p], nv);
            }
            unpack2(a0B, l0, h0);
            unpack2(a1B, l1, h1);
            {
                float s0 = fmaxf(l0 + h0 + bd0, 0.0f);
                float s1 = fmaxf(l1 + h1 + bd1, 0.0f);
                ull nv = ffma2(dt2, pack2(s0, s1), out2B[p]);
                dnewB[p] = ffma2(dsB, nrowB[p], nv);
            }
        }
#pragma unroll
        for (int p = 0; p < 25; ++p) { out2A[p] = dnewA[p]; out2B[p] = dnewB[p]; }

        // refill own slice for step l+1 (this thread is done reading it)
        if (l + 1 < L_STEPS) {
            const float* nsrc = noise + (size_t)(l + 1) * B_ROWS * 50 + sliceOff;
            #pragma unroll
            for (int i = 0; i < 25; ++i)
                cp16(mySlice + i * 4, nsrc + i * 4);
            asm volatile("cp.async.commit_group;" ::: "memory");
        }
    }

    // ================= epilogue: relu(out) @ Wfc^T + bfc -> (mean, sigma) =================
    const ull* w0 = (const ull*)(sWfc);
    const ull* w1 = (const ull*)(sWfc + 50);
    ull a0A = 0ull, a1A = 0ull, a0B = 0ull, a1B = 0ull;
#pragma unroll
    for (int p = 0; p < 25; ++p) {
        float lo, hi;
        unpack2(out2A[p], lo, hi);
        ull rA = pack2(fmaxf(lo, 0.0f), fmaxf(hi, 0.0f));
        unpack2(out2B[p], lo, hi);
        ull rB = pack2(fmaxf(lo, 0.0f), fmaxf(hi, 0.0f));
        ull wv0 = w0[p], wv1 = w1[p];
        a0A = ffma2(wv0, rA, a0A);
        a1A = ffma2(wv1, rA, a1A);
        a0B = ffma2(wv0, rB, a0B);
        a1B = ffma2(wv1, rB, a1B);
    }
    float m0, m1, z0, z1;
    const float bfc0 = smisc[1], bfc1 = smisc[2];

    unpack2(a0A, m0, m1);
    unpack2(a1A, z0, z1);
    {
        const float mean = m0 + m1 + bfc0;
        const float z    = z0 + z1 + bfc1;
        const float sp   = log1pf(expf(-fabsf(z))) + fmaxf(z, 0.0f);
        out[rowA] = mean;
        out[B_ROWS + rowA] = sp + 0.001f;
    }
    unpack2(a0B, m0, m1);
    unpack2(a1B, z0, z1);
    {
        const float mean = m0 + m1 + bfc0;
        const float z    = z0 + z1 + bfc1;
        const float sp   = log1pf(expf(-fabsf(z))) + fmaxf(z, 0.0f);
        out[rowB] = mean;
        out[B_ROWS + rowB] = sp + 0.001f;
    }
}

extern "C" void kernel_launch(void* const* d_in, const int* in_sizes, int n_in,
                              void* d_out, int out_size) {
    (void)in_sizes; (void)n_in; (void)out_size;
    const float* x      = (const float*)d_in[0];
    const float* Wd     = (const float*)d_in[1];
    const float* bd     = (const float*)d_in[2];
    const float* Wdrift = (const float*)d_in[3];
    const float* bdrift = (const float*)d_in[4];
    const float* W1     = (const float*)d_in[5];
    const float* b1     = (const float*)d_in[6];
    const float* W2     = (const float*)d_in[7];
    const float* b2     = (const float*)d_in[8];
    const float* Wfc    = (const float*)d_in[9];
    const float* bfc    = (const float*)d_in[10];
    const float* noise  = (const float*)d_in[11];
    float* out = (float*)d_out;

    cudaFuncSetAttribute(sdenet_kernel,
                         cudaFuncAttributeMaxDynamicSharedMemorySize, SMEM_BYTES);
    sdenet_kernel<<<GRID, TPB, SMEM_BYTES>>>(x, Wd, bd, Wdrift, bdrift,
                                             W1, b1, W2, b2, Wfc, bfc, noise, out);
}

// round 12
// speedup vs baseline: 1.1719x; 1.1719x over previous
#include <cuda_runtime.h>
#include <cstdint>
#include <math.h>

typedef unsigned long long ull;

static constexpr int B_ROWS = 262144;
static constexpr int L_STEPS = 20;
static constexpr int TPB = 64;
static constexpr int ROWS_PER_CTA = 2 * TPB;                 // 128
static constexpr int GRID = B_ROWS / ROWS_PER_CTA;           // 2048

// Wdrift mirrored into constant memory (10 KB). Even rows are read from here
// (const port, broadcast-friendly); odd rows from SMEM (L1 port). This splits
// the weight stream across two independent read paths.
__constant__ float cWdr[2500];   // [50,50] row-major, row offset 200B = 16B-aligned

// ---- shared memory layout (floats) ----
static constexpr int OFF_WDR   = 0;            // [50*52] (only odd rows read in main loop)
static constexpr int OFF_BDR   = 2600;
static constexpr int OFF_BD    = 2650;
static constexpr int OFF_B1    = 2700;
static constexpr int OFF_W2    = 2800;
static constexpr int OFF_WFC   = 2900;
static constexpr int OFF_MISC  = 3000;
static constexpr int OFF_BUF   = 3008;                        // 16B aligned
static constexpr int NOISE_TILE = ROWS_PER_CTA * 50;          // 6400 floats (25.6 KB)
static constexpr int SMEM_FLOATS = OFF_BUF + NOISE_TILE;      // 9408
static constexpr int SMEM_BYTES  = SMEM_FLOATS * 4;           // 37632 -> 5 CTAs/SM

// ---- packed f32x2 helpers (Blackwell 2x-fp32 path; PTX-only) ----
static __device__ __forceinline__ ull ffma2(ull a, ull b, ull c) {
    ull d;
    asm("fma.rn.f32x2 %0, %1, %2, %3;" : "=l"(d) : "l"(a), "l"(b), "l"(c));
    return d;
}
static __device__ __forceinline__ ull pack2(float lo, float hi) {
    ull r;
    asm("mov.b64 %0, {%1, %2};" : "=l"(r) : "f"(lo), "f"(hi));
    return r;
}
static __device__ __forceinline__ void unpack2(ull v, float& lo, float& hi) {
    asm("mov.b64 {%0, %1}, %2;" : "=f"(lo), "=f"(hi) : "l"(v));
}

static __device__ __forceinline__ unsigned smem_u32(const void* p) {
    return (unsigned)__cvta_generic_to_shared(p);
}
static __device__ __forceinline__ void cp16(void* sdst, const void* gsrc) {
    asm volatile("cp.async.cg.shared.global [%0], [%1], 16;"
                 :: "r"(smem_u32(sdst)), "l"(gsrc) : "memory");
}

// Prologue dot for one row, chunked partial sums (bounded register pressure).
static __device__ __forceinline__ void prologue_row(const float* __restrict__ xrow,
                                                    const float* __restrict__ sWd,
                                                    const float* __restrict__ sbd,
                                                    ull* __restrict__ out2) {
#pragma unroll
    for (int p = 0; p < 25; ++p) out2[p] = pack2(sbd[2 * p], sbd[2 * p + 1]);

    for (int c = 0; c < 3; ++c) {
        ull xv[16];
        const ull* xr = (const ull*)xrow + c * 16;
        if (c < 2) {
#pragma unroll
            for (int t = 0; t < 16; ++t) xv[t] = xr[t];
        } else {
#pragma unroll
            for (int t = 0; t < 13; ++t) xv[t] = xr[t];
            xv[13] = 0ull; xv[14] = 0ull; xv[15] = 0ull;   // Wd cols 90..95 are 0
        }
#pragma unroll 5
        for (int p = 0; p < 25; ++p) {
            const ulonglong2* w0 = (const ulonglong2*)(sWd + (2 * p) * 96 + c * 32);
            const ulonglong2* w1 = (const ulonglong2*)(sWd + (2 * p + 1) * 96 + c * 32);
            ull a0 = 0ull, a1 = 0ull;
#pragma unroll
            for (int q = 0; q < 8; ++q) {
                ulonglong2 wa = w0[q];
                a0 = ffma2(wa.x, xv[2 * q],     a0);
                a0 = ffma2(wa.y, xv[2 * q + 1], a0);
                ulonglong2 wb = w1[q];
                a1 = ffma2(wb.x, xv[2 * q],     a1);
                a1 = ffma2(wb.y, xv[2 * q + 1], a1);
            }
            float l0, h0, l1, h1, o0, o1;
            unpack2(a0, l0, h0);
            unpack2(a1, l1, h1);
            unpack2(out2[p], o0, o1);
            out2[p] = pack2(o0 + l0 + h0, o1 + l1 + h1);
        }
    }
}

__global__ void __launch_bounds__(TPB, 5)   // 5 CTAs/SM -> 10 warps/SM, reg cap 204
sdenet_kernel(const float* __restrict__ x,      // [B,90]
              const float* __restrict__ Wd,     // [50,90]
              const float* __restrict__ bd,     // [50]
              const float* __restrict__ Wdrift, // [50,50]
              const float* __restrict__ bdrift, // [50]
              const float* __restrict__ W1,     // [100,50]
              const float* __restrict__ b1,     // [100]
              const float* __restrict__ W2,     // [1,100]
              const float* __restrict__ b2,     // [1]
              const float* __restrict__ Wfc,    // [2,50]
              const float* __restrict__ bfc,    // [2]
              const float* __restrict__ noise,  // [L,B,50]
              float* __restrict__ out)          // [2*B] = mean(B) ++ sigma(B)
{
    extern __shared__ float smem[];
    float* sWdr  = smem + OFF_WDR;
    float* sbdr  = smem + OFF_BDR;
    float* sbd   = smem + OFF_BD;
    float* sb1   = smem + OFF_B1;
    float* sW2   = smem + OFF_W2;
    float* sWfc  = smem + OFF_WFC;
    float* smisc = smem + OFF_MISC;
    float* sBuf  = smem + OFF_BUF;
    float* sWd   = sBuf;             // phase-1a alias (4800 <= 6400)
    float* sW1   = sBuf;             // phase-1b alias (5200 <= 6400)

    const int tid = threadIdx.x;
    const size_t rowBase = (size_t)blockIdx.x * ROWS_PER_CTA;
    const int rowA = (int)rowBase + tid;
    const int rowB = rowA + TPB;

    // ---- stage persistent weights + Wd (into buffer alias) ----
    for (int i = tid; i < 4800; i += TPB) {
        int r = i / 96, k = i - r * 96;
        sWd[i] = (k < 90) ? Wd[r * 90 + k] : 0.0f;
    }
    for (int i = tid; i < 2500; i += TPB) {
        int j = i / 50, k = i - j * 50;
        sWdr[j * 52 + k] = Wdrift[i];
    }
    for (int i = tid; i < 100; i += TPB) {
        sW2[i]  = W2[i];
        sb1[i]  = b1[i];
        sWfc[i] = Wfc[i];
    }
    if (tid < 50)  sbd[tid]  = bd[tid];
    if (tid < 50)  sbdr[tid] = bdrift[tid];
    if (tid == 0) { smisc[0] = b2[0]; smisc[1] = bfc[0]; smisc[2] = bfc[1]; }
    __syncthreads();

    // ================= prologue: out = x @ Wd^T + bd =================
    ull out2A[25], out2B[25];
    prologue_row(x + (size_t)rowA * 90, sWd, sbd, out2A);
    prologue_row(x + (size_t)rowB * 90, sWd, sbd, out2B);

    __syncthreads();   // done reading Wd; buffer free for W1

    // ---- stage W1 (into buffer alias) ----
    for (int i = tid; i < 5000; i += TPB) {
        int m = i / 50, k = i - m * 50;
        sW1[m * 52 + k] = W1[i];
    }
    __syncthreads();

    // ====== diffusion = 0.5*sigmoid(relu(out@W1^T+b1) @ W2^T + b2) ======
    float daccA = smisc[0], daccB = smisc[0];
#pragma unroll 2
    for (int m = 0; m < 100; ++m) {
        const float* wrow = sW1 + m * 52;
        const ulonglong2* w2r = (const ulonglong2*)wrow;
        ull aA = 0ull, aB = 0ull;
#pragma unroll
        for (int q = 0; q < 12; ++q) {
            ulonglong2 w = w2r[q];
            aA = ffma2(w.x, out2A[2 * q],     aA);
            aA = ffma2(w.y, out2A[2 * q + 1], aA);
            aB = ffma2(w.x, out2B[2 * q],     aB);
            aB = ffma2(w.y, out2B[2 * q + 1], aB);
        }
        ull wt = *(const ull*)(wrow + 48);
        aA = ffma2(wt, out2A[24], aA);
        aB = ffma2(wt, out2B[24], aB);
        float lA, hA, lB, hB;
        unpack2(aA, lA, hA);
        unpack2(aB, lB, hB);
        float bm = sb1[m], w2m = sW2[m];
        daccA = fmaf(w2m, fmaxf(lA + hA + bm, 0.0f), daccA);
        daccB = fmaf(w2m, fmaxf(lB + hB + bm, 0.0f), daccB);
    }
    const float dt   = 4.0f / 20.0f;
    const float sqdt = sqrtf(dt);
    const float diffA = 0.5f / (1.0f + expf(-daccA));
    const float diffB = 0.5f / (1.0f + expf(-daccB));
    const ull dsA = pack2(diffA * sqdt, diffA * sqdt);
    const ull dsB = pack2(diffB * sqdt, diffB * sqdt);
    const ull dt2 = pack2(dt, dt);

    __syncthreads();   // done reading W1; buffer free for noise

    // ---- prefetch step-0 noise (cooperative, coalesced) ----
    {
        const float* nsrc = noise + rowBase * 50;
        for (int i = tid; i < NOISE_TILE / 4; i += TPB)
            cp16(sBuf + i * 4, nsrc + i * 4);
        asm volatile("cp.async.commit_group;" ::: "memory");
    }

    // Constant-space views of even Wdrift rows: row 2p at float offset 100p
    // (byte offset 400p, 16B aligned). 12 x 16B + 1 x 8B per row.
    const ulonglong2* cW16 = (const ulonglong2*)cWdr;   // 16B units
    const ull*        cW8  = (const ull*)cWdr;          // 8B units

    // ================= main SDE loop (single buffer, refill per step) =================
#pragma unroll 1
    for (int l = 0; l < L_STEPS; ++l) {
        asm volatile("cp.async.wait_group 0;" ::: "memory");
        __syncthreads();   // noise l visible to all threads

        const ull* nrowA = (const ull*)(sBuf + tid * 50);
        const ull* nrowB = (const ull*)(sBuf + (tid + TPB) * 50);

        ull dnewA[25], dnewB[25];
#pragma unroll 5
        for (int p = 0; p < 25; ++p) {
            // even row 2p from CONSTANT memory (const port)
            const ulonglong2* w02 = cW16 + 25 * p;       // float offset 100p
            // odd row 2p+1 from SMEM (L1 port)
            const float* w1 = sWdr + (2 * p + 1) * 52;
            const ulonglong2* w12 = (const ulonglong2*)w1;
            ull a0A = 0ull, a1A = 0ull, a0B = 0ull, a1B = 0ull;
#pragma unroll
            for (int q = 0; q < 12; ++q) {
                ulonglong2 wa = w02[q];
                a0A = ffma2(wa.x, out2A[2 * q],     a0A);
                a0A = ffma2(wa.y, out2A[2 * q + 1], a0A);
                a0B = ffma2(wa.x, out2B[2 * q],     a0B);
                a0B = ffma2(wa.y, out2B[2 * q + 1], a0B);
                ulonglong2 wb = w12[q];
                a1A = ffma2(wb.x, out2A[2 * q],     a1A);
                a1A = ffma2(wb.y, out2A[2 * q + 1], a1A);
                a1B = ffma2(wb.x, out2B[2 * q],     a1B);
                a1B = ffma2(wb.y, out2B[2 * q + 1], a1B);
            }
            ull wt0 = cW8[50 * p + 24];                  // row 2p floats 48..49
            ull wt1 = *(const ull*)(w1 + 48);
            a0A = ffma2(wt0, out2A[24], a0A);
            a1A = ffma2(wt1, out2A[24], a1A);
            a0B = ffma2(wt0, out2B[24], a0B);
            a1B = ffma2(wt1, out2B[24], a1B);

            float l0, h0, l1, h1;
            const float bd0 = sbdr[2 * p], bd1 = sbdr[2 * p + 1];

            unpack2(a0A, l0, h0);
            unpack2(a1A, l1, h1);
            {
                float s0 = fmaxf(l0 + h0 + bd0, 0.0f);
                float s1 = fmaxf(l1 + h1 + bd1, 0.0f);
                ull nv = ffma2(dt2, pack2(s0, s1), out2A[p]);
                dnewA[p] = ffma2(dsA, nrowA[p], nv);
            }
            unpack2(a0B, l0, h0);
            unpack2(a1B, l1, h1);
            {
                float s0 = fmaxf(l0 + h0 + bd0, 0.0f);
                float s1 = fmaxf(l1 + h1 + bd1, 0.0f);
                ull nv = ffma2(dt2, pack2(s0, s1), out2B[p]);
                dnewB[p] = ffma2(dsB, nrowB[p], nv);
            }
        }
#pragma unroll
        for (int p = 0; p < 25; ++p) { out2A[p] = dnewA[p]; out2B[p] = dnewB[p]; }

        __syncthreads();   // all threads done reading buffer

        if (l + 1 < L_STEPS) {
            const float* nsrc = noise + ((size_t)(l + 1) * B_ROWS + rowBase) * 50;
            for (int i = tid; i < NOISE_TILE / 4; i += TPB)
                cp16(sBuf + i * 4, nsrc + i * 4);
            asm volatile("cp.async.commit_group;" ::: "memory");
        }
    }

    // ================= epilogue: relu(out) @ Wfc^T + bfc -> (mean, sigma) =================
    const ull* w0 = (const ull*)(sWfc);
    const ull* w1 = (const ull*)(sWfc + 50);
    ull a0A = 0ull, a1A = 0ull, a0B = 0ull, a1B = 0ull;
#pragma unroll
    for (int p = 0; p < 25; ++p) {
        float lo, hi;
        unpack2(out2A[p], lo, hi);
        ull rA = pack2(fmaxf(lo, 0.0f), fmaxf(hi, 0.0f));
        unpack2(out2B[p], lo, hi);
        ull rB = pack2(fmaxf(lo, 0.0f), fmaxf(hi, 0.0f));
        ull wv0 = w0[p], wv1 = w1[p];
        a0A = ffma2(wv0, rA, a0A);
        a1A = ffma2(wv1, rA, a1A);
        a0B = ffma2(wv0, rB, a0B);
        a1B = ffma2(wv1, rB, a1B);
    }
    float m0, m1, z0, z1;
    const float bfc0 = smisc[1], bfc1 = smisc[2];

    unpack2(a0A, m0, m1);
    unpack2(a1A, z0, z1);
    {
        const float mean = m0 + m1 + bfc0;
        const float z    = z0 + z1 + bfc1;
        const float sp   = log1pf(expf(-fabsf(z))) + fmaxf(z, 0.0f);
        out[rowA] = mean;
        out[B_ROWS + rowA] = sp + 0.001f;
    }
    unpack2(a0B, m0, m1);
    unpack2(a1B, z0, z1);
    {
        const float mean = m0 + m1 + bfc0;
        const float z    = z0 + z1 + bfc1;
        const float sp   = log1pf(expf(-fabsf(z))) + fmaxf(z, 0.0f);
        out[rowB] = mean;
        out[B_ROWS + rowB] = sp + 0.001f;
    }
}

extern "C" void kernel_launch(void* const* d_in, const int* in_sizes, int n_in,
                              void* d_out, int out_size) {
    (void)in_sizes; (void)n_in; (void)out_size;
    const float* x      = (const float*)d_in[0];
    const float* Wd     = (const float*)d_in[1];
    const float* bd     = (const float*)d_in[2];
    const float* Wdrift = (const float*)d_in[3];
    const float* bdrift = (const float*)d_in[4];
    const float* W1     = (const float*)d_in[5];
    const float* b1     = (const float*)d_in[6];
    const float* W2     = (const float*)d_in[7];
    const float* b2     = (const float*)d_in[8];
    const float* Wfc    = (const float*)d_in[9];
    const float* bfc    = (const float*)d_in[10];
    const float* noise  = (const float*)d_in[11];
    float* out = (float*)d_out;

    // Mirror Wdrift into constant memory (D2D async copy: graph-capturable,
    // allocation-free, deterministic).
    cudaMemcpyToSymbolAsync(cWdr, Wdrift, 2500 * sizeof(float), 0,
                            cudaMemcpyDeviceToDevice);

    cudaFuncSetAttribute(sdenet_kernel,
                         cudaFuncAttributeMaxDynamicSharedMemorySize, SMEM_BYTES);
    sdenet_kernel<<<GRID, TPB, SMEM_BYTES>>>(x, Wd, bd, Wdrift, bdrift,
                                             W1, b1, W2, b2, Wfc, bfc, noise, out);
}

// round 13
// speedup vs baseline: 1.2112x; 1.0335x over previous
#include <cuda_runtime.h>
#include <cstdint>
#include <math.h>

typedef unsigned long long ull;

static constexpr int B_ROWS = 262144;
static constexpr int L_STEPS = 20;
static constexpr int TPB = 64;
static constexpr int ROWS_PER_CTA = 2 * TPB;                 // 128
static constexpr int GRID = B_ROWS / ROWS_PER_CTA;           // 2048

// Wdrift mirrored into constant memory: even rows read via const port,
// odd rows via SMEM/L1 port (two independent read paths).
__constant__ float cWdr[2500];   // [50,50] row-major

// ---- shared memory layout (floats) ----
static constexpr int OFF_WDR   = 0;            // [50*52] (odd rows read in main loop)
static constexpr int OFF_BDR   = 2600;
static constexpr int OFF_BD    = 2650;
static constexpr int OFF_B1    = 2700;
static constexpr int OFF_W2    = 2800;
static constexpr int OFF_WFC   = 2900;
static constexpr int OFF_MISC  = 3000;
static constexpr int OFF_BUF   = 3008;                        // 16B aligned
static constexpr int NOISE_TILE = ROWS_PER_CTA * 50;          // 6400 floats (25.6 KB)
static constexpr int SMEM_FLOATS = OFF_BUF + NOISE_TILE;      // 9408
static constexpr int SMEM_BYTES  = SMEM_FLOATS * 4;           // 37632 -> 5 CTAs/SM

// Per-warp noise slice: warp w owns CTA rows [64w, 64w+64) -> floats
// [3200w, 3200w+3200) of the buffer, contiguous in gmem AND smem.
static constexpr int WARP_SLICE = 3200;        // floats
static constexpr int WARP_CHUNKS = WARP_SLICE / 4;   // 800 x 16B -> 25 per lane

// ---- packed f32x2 helpers (Blackwell 2x-fp32 path; PTX-only) ----
static __device__ __forceinline__ ull ffma2(ull a, ull b, ull c) {
    ull d;
    asm("fma.rn.f32x2 %0, %1, %2, %3;" : "=l"(d) : "l"(a), "l"(b), "l"(c));
    return d;
}
static __device__ __forceinline__ ull pack2(float lo, float hi) {
    ull r;
    asm("mov.b64 %0, {%1, %2};" : "=l"(r) : "f"(lo), "f"(hi));
    return r;
}
static __device__ __forceinline__ void unpack2(ull v, float& lo, float& hi) {
    asm("mov.b64 {%0, %1}, %2;" : "=f"(lo), "=f"(hi) : "l"(v));
}

static __device__ __forceinline__ unsigned smem_u32(const void* p) {
    return (unsigned)__cvta_generic_to_shared(p);
}
static __device__ __forceinline__ void cp16(void* sdst, const void* gsrc) {
    asm volatile("cp.async.cg.shared.global [%0], [%1], 16;"
                 :: "r"(smem_u32(sdst)), "l"(gsrc) : "memory");
}

// Prologue dot for one row, chunked partial sums (bounded register pressure).
static __device__ __forceinline__ void prologue_row(const float* __restrict__ xrow,
                                                    const float* __restrict__ sWd,
                                                    const float* __restrict__ sbd,
                                                    ull* __restrict__ out2) {
#pragma unroll
    for (int p = 0; p < 25; ++p) out2[p] = pack2(sbd[2 * p], sbd[2 * p + 1]);

    for (int c = 0; c < 3; ++c) {
        ull xv[16];
        const ull* xr = (const ull*)xrow + c * 16;
        if (c < 2) {
#pragma unroll
            for (int t = 0; t < 16; ++t) xv[t] = xr[t];
        } else {
#pragma unroll
            for (int t = 0; t < 13; ++t) xv[t] = xr[t];
            xv[13] = 0ull; xv[14] = 0ull; xv[15] = 0ull;   // Wd cols 90..95 are 0
        }
#pragma unroll 5
        for (int p = 0; p < 25; ++p) {
            const ulonglong2* w0 = (const ulonglong2*)(sWd + (2 * p) * 96 + c * 32);
            const ulonglong2* w1 = (const ulonglong2*)(sWd + (2 * p + 1) * 96 + c * 32);
            ull a0 = 0ull, a1 = 0ull;
#pragma unroll
            for (int q = 0; q < 8; ++q) {
                ulonglong2 wa = w0[q];
                a0 = ffma2(wa.x, xv[2 * q],     a0);
                a0 = ffma2(wa.y, xv[2 * q + 1], a0);
                ulonglong2 wb = w1[q];
                a1 = ffma2(wb.x, xv[2 * q],     a1);
                a1 = ffma2(wb.y, xv[2 * q + 1], a1);
            }
            float l0, h0, l1, h1, o0, o1;
            unpack2(a0, l0, h0);
            unpack2(a1, l1, h1);
            unpack2(out2[p], o0, o1);
            out2[p] = pack2(o0 + l0 + h0, o1 + l1 + h1);
        }
    }
}

__global__ void __launch_bounds__(TPB, 5)   // 5 CTAs/SM -> 10 warps/SM, reg cap 204
sdenet_kernel(const float* __restrict__ x,      // [B,90]
              const float* __restrict__ Wd,     // [50,90]
              const float* __restrict__ bd,     // [50]
              const float* __restrict__ Wdrift, // [50,50]
              const float* __restrict__ bdrift, // [50]
              const float* __restrict__ W1,     // [100,50]
              const float* __restrict__ b1,     // [100]
              const float* __restrict__ W2,     // [1,100]
              const float* __restrict__ b2,     // [1]
              const float* __restrict__ Wfc,    // [2,50]
              const float* __restrict__ bfc,    // [2]
              const float* __restrict__ noise,  // [L,B,50]
              float* __restrict__ out)          // [2*B] = mean(B) ++ sigma(B)
{
    extern __shared__ float smem[];
    float* sWdr  = smem + OFF_WDR;
    float* sbdr  = smem + OFF_BDR;
    float* sbd   = smem + OFF_BD;
    float* sb1   = smem + OFF_B1;
    float* sW2   = smem + OFF_W2;
    float* sWfc  = smem + OFF_WFC;
    float* smisc = smem + OFF_MISC;
    float* sBuf  = smem + OFF_BUF;
    float* sWd   = sBuf;             // phase-1a alias (4800 <= 6400)
    float* sW1   = sBuf;             // phase-1b alias (5200 <= 6400)

    const int tid  = threadIdx.x;
    const int warp = tid >> 5;       // 0 or 1
    const int lane = tid & 31;
    const size_t rowBase = (size_t)blockIdx.x * ROWS_PER_CTA;

    // Warp-contiguous row mapping: warp w handles CTA rows [64w, 64w+64);
    // this thread: rows 64w+lane and 64w+32+lane.
    const int ctaRowA = 64 * warp + lane;
    const int ctaRowB = ctaRowA + 32;
    const int rowA = (int)rowBase + ctaRowA;
    const int rowB = (int)rowBase + ctaRowB;

    // Warp-private noise slice (contiguous 12.8 KB in smem and gmem)
    float* wSlice = sBuf + warp * WARP_SLICE;
    const size_t wSliceOff = rowBase * 50 + (size_t)warp * WARP_SLICE;

    // ---- stage persistent weights + Wd (into buffer alias) ----
    for (int i = tid; i < 4800; i += TPB) {
        int r = i / 96, k = i - r * 96;
        sWd[i] = (k < 90) ? Wd[r * 90 + k] : 0.0f;
    }
    for (int i = tid; i < 2500; i += TPB) {
        int j = i / 50, k = i - j * 50;
        sWdr[j * 52 + k] = Wdrift[i];
    }
    for (int i = tid; i < 100; i += TPB) {
        sW2[i]  = W2[i];
        sb1[i]  = b1[i];
        sWfc[i] = Wfc[i];
    }
    if (tid < 50)  sbd[tid]  = bd[tid];
    if (tid < 50)  sbdr[tid] = bdrift[tid];
    if (tid == 0) { smisc[0] = b2[0]; smisc[1] = bfc[0]; smisc[2] = bfc[1]; }
    __syncthreads();

    // ================= prologue: out = x @ Wd^T + bd =================
    ull out2A[25], out2B[25];
    prologue_row(x + (size_t)rowA * 90, sWd, sbd, out2A);
    prologue_row(x + (size_t)rowB * 90, sWd, sbd, out2B);

    __syncthreads();   // done reading Wd; buffer free for W1

    // ---- stage W1 (into buffer alias) ----
    for (int i = tid; i < 5000; i += TPB) {
        int m = i / 50, k = i - m * 50;
        sW1[m * 52 + k] = W1[i];
    }
    __syncthreads();

    // ====== diffusion = 0.5*sigmoid(relu(out@W1^T+b1) @ W2^T + b2) ======
    float daccA = smisc[0], daccB = smisc[0];
#pragma unroll 2
    for (int m = 0; m < 100; ++m) {
        const float* wrow = sW1 + m * 52;
        const ulonglong2* w2r = (const ulonglong2*)wrow;
        ull aA = 0ull, aB = 0ull;
#pragma unroll
        for (int q = 0; q < 12; ++q) {
            ulonglong2 w = w2r[q];
            aA = ffma2(w.x, out2A[2 * q],     aA);
            aA = ffma2(w.y, out2A[2 * q + 1], aA);
            aB = ffma2(w.x, out2B[2 * q],     aB);
            aB = ffma2(w.y, out2B[2 * q + 1], aB);
        }
        ull wt = *(const ull*)(wrow + 48);
        aA = ffma2(wt, out2A[24], aA);
        aB = ffma2(wt, out2B[24], aB);
        float lA, hA, lB, hB;
        unpack2(aA, lA, hA);
        unpack2(aB, lB, hB);
        float bm = sb1[m], w2m = sW2[m];
        daccA = fmaf(w2m, fmaxf(lA + hA + bm, 0.0f), daccA);
        daccB = fmaf(w2m, fmaxf(lB + hB + bm, 0.0f), daccB);
    }
    const float dt   = 4.0f / 20.0f;
    const float sqdt = sqrtf(dt);
    const float diffA = 0.5f / (1.0f + expf(-daccA));
    const float diffB = 0.5f / (1.0f + expf(-daccB));
    const ull dsA = pack2(diffA * sqdt, diffA * sqdt);
    const ull dsB = pack2(diffB * sqdt, diffB * sqdt);
    const ull dt2 = pack2(dt, dt);

    __syncthreads();   // done reading W1; buffer free for noise (LAST CTA barrier)

    // ---- per-warp prefetch of step-0 noise slice (coalesced 12.8 KB) ----
    {
        const float* nsrc = noise + wSliceOff;
#pragma unroll
        for (int i = 0; i < 25; ++i) {
            int c = lane + 32 * i;
            cp16(wSlice + c * 4, nsrc + c * 4);
        }
        asm volatile("cp.async.commit_group;" ::: "memory");
    }

    // Constant-space views of even Wdrift rows.
    const ulonglong2* cW16 = (const ulonglong2*)cWdr;
    const ull*        cW8  = (const ull*)cWdr;

    // ================= main SDE loop: warp-scoped sync only =================
#pragma unroll 1
    for (int l = 0; l < L_STEPS; ++l) {
        asm volatile("cp.async.wait_group 0;" ::: "memory");   // own group done
        __syncwarp();   // all lanes' cp.asyncs complete -> slice visible warp-wide

        const ull* nrowA = (const ull*)(wSlice + lane * 50);
        const ull* nrowB = (const ull*)(wSlice + 1600 + lane * 50);

        ull dnewA[25], dnewB[25];
#pragma unroll 5
        for (int p = 0; p < 25; ++p) {
            const ulonglong2* w02 = cW16 + 25 * p;            // even row: const port
            const float* w1 = sWdr + (2 * p + 1) * 52;        // odd row: L1 port
            const ulonglong2* w12 = (const ulonglong2*)w1;
            ull a0A = 0ull, a1A = 0ull, a0B = 0ull, a1B = 0ull;
#pragma unroll
            for (int q = 0; q < 12; ++q) {
                ulonglong2 wa = w02[q];
                a0A = ffma2(wa.x, out2A[2 * q],     a0A);
                a0A = ffma2(wa.y, out2A[2 * q + 1], a0A);
                a0B = ffma2(wa.x, out2B[2 * q],     a0B);
                a0B = ffma2(wa.y, out2B[2 * q + 1], a0B);
                ulonglong2 wb = w12[q];
                a1A = ffma2(wb.x, out2A[2 * q],     a1A);
                a1A = ffma2(wb.y, out2A[2 * q + 1], a1A);
                a1B = ffma2(wb.x, out2B[2 * q],     a1B);
                a1B = ffma2(wb.y, out2B[2 * q + 1], a1B);
            }
            ull wt0 = cW8[50 * p + 24];
            ull wt1 = *(const ull*)(w1 + 48);
            a0A = ffma2(wt0, out2A[24], a0A);
            a1A = ffma2(wt1, out2A[24], a1A);
            a0B = ffma2(wt0, out2B[24], a0B);
            a1B = ffma2(wt1, out2B[24], a1B);

            float l0, h0, l1, h1;
            const float bd0 = sbdr[2 * p], bd1 = sbdr[2 * p + 1];

            unpack2(a0A, l0, h0);
            unpack2(a1A, l1, h1);
            {
                float s0 = fmaxf(l0 + h0 + bd0, 0.0f);
                float s1 = fmaxf(l1 + h1 + bd1, 0.0f);
                ull nv = ffma2(dt2, pack2(s0, s1), out2A[p]);
                dnewA[p] = ffma2(dsA, nrowA[p], nv);
            }
            unpack2(a0B, l0, h0);
            unpack2(a1B, l1, h1);
            {
                float s0 = fmaxf(l0 + h0 + bd0, 0.0f);
                float s1 = fmaxf(l1 + h1 + bd1, 0.0f);
                ull nv = ffma2(dt2, pack2(s0, s1), out2B[p]);
                dnewB[p] = ffma2(dsB, nrowB[p], nv);
            }
        }
#pragma unroll
        for (int p = 0; p < 25; ++p) { out2A[p] = dnewA[p]; out2B[p] = dnewB[p]; }

        __syncwarp();   // all lanes done READING the slice before overwrite

        if (l + 1 < L_STEPS) {
            const float* nsrc = noise + (size_t)(l + 1) * B_ROWS * 50 + wSliceOff;
#pragma unroll
            for (int i = 0; i < 25; ++i) {
                int c = lane + 32 * i;
                cp16(wSlice + c * 4, nsrc + c * 4);
            }
            asm volatile("cp.async.commit_group;" ::: "memory");
        }
    }

    // ================= epilogue: relu(out) @ Wfc^T + bfc -> (mean, sigma) =================
    const ull* w0 = (const ull*)(sWfc);
    const ull* w1 = (const ull*)(sWfc + 50);
    ull a0A = 0ull, a1A = 0ull, a0B = 0ull, a1B = 0ull;
#pragma unroll
    for (int p = 0; p < 25; ++p) {
        float lo, hi;
        unpack2(out2A[p], lo, hi);
        ull rA = pack2(fmaxf(lo, 0.0f), fmaxf(hi, 0.0f));
        unpack2(out2B[p], lo, hi);
        ull rB = pack2(fmaxf(lo, 0.0f), fmaxf(hi, 0.0f));
        ull wv0 = w0[p], wv1 = w1[p];
        a0A = ffma2(wv0, rA, a0A);
        a1A = ffma2(wv1, rA, a1A);
        a0B = ffma2(wv0, rB, a0B);
        a1B = ffma2(wv1, rB, a1B);
    }
    float m0, m1, z0, z1;
    const float bfc0 = smisc[1], bfc1 = smisc[2];

    unpack2(a0A, m0, m1);
    unpack2(a1A, z0, z1);
    {
        const float mean = m0 + m1 + bfc0;
        const float z    = z0 + z1 + bfc1;
        const float sp   = log1pf(expf(-fabsf(z))) + fmaxf(z, 0.0f);
        out[rowA] = mean;
        out[B_ROWS + rowA] = sp + 0.001f;
    }
    unpack2(a0B, m0, m1);
    unpack2(a1B, z0, z1);
    {
        const float mean = m0 + m1 + bfc0;
        const float z    = z0 + z1 + bfc1;
        const float sp   = log1pf(expf(-fabsf(z))) + fmaxf(z, 0.0f);
        out[rowB] = mean;
        out[B_ROWS + rowB] = sp + 0.001f;
    }
}

extern "C" void kernel_launch(void* const* d_in, const int* in_sizes, int n_in,
                              void* d_out, int out_size) {
    (void)in_sizes; (void)n_in; (void)out_size;
    const float* x      = (const float*)d_in[0];
    const float* Wd     = (const float*)d_in[1];
    const float* bd     = (const float*)d_in[2];
    const float* Wdrift = (const float*)d_in[3];
    const float* bdrift = (const float*)d_in[4];
    const float* W1     = (const float*)d_in[5];
    const float* b1     = (const float*)d_in[6];
    const float* W2     = (const float*)d_in[7];
    const float* b2     = (const float*)d_in[8];
    const float* Wfc    = (const float*)d_in[9];
    const float* bfc    = (const float*)d_in[10];
    const float* noise  = (const float*)d_in[11];
    float* out = (float*)d_out;

    cudaMemcpyToSymbolAsync(cWdr, Wdrift, 2500 * sizeof(float), 0,
                            cudaMemcpyDeviceToDevice);

    cudaFuncSetAttribute(sdenet_kernel,
                         cudaFuncAttributeMaxDynamicSharedMemorySize, SMEM_BYTES);
    sdenet_kernel<<<GRID, TPB, SMEM_BYTES>>>(x, Wd, bd, Wdrift, bdrift,
                                             W1, b1, W2, b2, Wfc, bfc, noise, out);
}